// round 2
// baseline (speedup 1.0000x reference)
#include <cuda_runtime.h>

// Problem constants (fixed by the dataset)
#define NN   50000
#define NE   800000
#define NF   64
#define NIN  256
#define DEPTH 4

// ---------------- device scratch (static allocation only) ----------------
__device__ float g_X[NN * NF];      // current node features
__device__ float g_XWc[NN * NF];    // X @ conv_w
__device__ float g_XWg[NN * NF];    // X @ gg_w
__device__ float g_Xn[NN * NF];     // relu(gcn_conv(X, conv_w)) = X_
__device__ float g_xg[NN * NF];     // relu(gcn_conv(X, gg_w))
__device__ float g_dis[NN];         // rsqrt(in_deg + 1)
__device__ float g_invcnt[NN];      // 1 / max(out_deg, 1)
__device__ int   g_deg_in[NN];
__device__ int   g_deg_out[NN];
__device__ int   g_rp_in[NN + 1];
__device__ int   g_rp_out[NN + 1];
__device__ int   g_cur_in[NN];
__device__ int   g_cur_out[NN];
__device__ int   g_col_in[NE];      // src ids, grouped by dst
__device__ int   g_col_out[NE];     // dst ids, grouped by src

// ---------------- f32x2 packed-FMA helpers (PTX-only on sm_10x) ----------
__device__ __forceinline__ unsigned long long pack2(float a, float b) {
    unsigned long long r;
    asm("mov.b64 %0, {%1, %2};" : "=l"(r) : "f"(a), "f"(b));
    return r;
}
__device__ __forceinline__ void fma2(unsigned long long& d,
                                     unsigned long long a,
                                     unsigned long long b) {
    asm("fma.rn.f32x2 %0, %1, %2, %0;" : "+l"(d) : "l"(a), "l"(b));
}
__device__ __forceinline__ float2 unpack2(unsigned long long v) {
    float2 r;
    asm("mov.b64 {%0, %1}, %2;" : "=f"(r.x), "=f"(r.y) : "l"(v));
    return r;
}

// ---------------- graph preprocessing ----------------
__global__ void zero_deg_kernel() {
    int i = blockIdx.x * blockDim.x + threadIdx.x;
    if (i < NN) { g_deg_in[i] = 0; g_deg_out[i] = 0; }
}

__global__ void count_kernel(const int* __restrict__ src, const int* __restrict__ dst) {
    int e = blockIdx.x * blockDim.x + threadIdx.x;
    if (e < NE) {
        atomicAdd(&g_deg_out[src[e]], 1);
        atomicAdd(&g_deg_in[dst[e]], 1);
    }
}

// Single-block exclusive scan over NN counts -> rp, cur; rp[NN] = total.
__global__ void scan_kernel(const int* __restrict__ cnt, int* __restrict__ rp,
                            int* __restrict__ cur) {
    __shared__ int wsum[32];
    __shared__ int s_carry;
    int t = threadIdx.x, lane = t & 31, wid = t >> 5;
    if (t == 0) s_carry = 0;
    __syncthreads();
    for (int base = 0; base < NN; base += 1024) {
        int i = base + t;
        int v = (i < NN) ? cnt[i] : 0;
        int x = v;
        #pragma unroll
        for (int d = 1; d < 32; d <<= 1) {
            int y = __shfl_up_sync(0xffffffffu, x, d);
            if (lane >= d) x += y;
        }
        if (lane == 31) wsum[wid] = x;
        __syncthreads();
        if (wid == 0) {
            int s = wsum[lane];
            #pragma unroll
            for (int d = 1; d < 32; d <<= 1) {
                int y = __shfl_up_sync(0xffffffffu, s, d);
                if (lane >= d) s += y;
            }
            wsum[lane] = s;
        }
        __syncthreads();
        int carry = s_carry;
        int pre = (wid > 0) ? wsum[wid - 1] : 0;
        int excl = carry + pre + x - v;
        if (i < NN) { rp[i] = excl; cur[i] = excl; }
        __syncthreads();
        if (t == 1023) s_carry = carry + wsum[31];
        __syncthreads();
    }
    if (t == 0) rp[NN] = s_carry;
}

__global__ void node_init_kernel() {
    int i = blockIdx.x * blockDim.x + threadIdx.x;
    if (i < NN) {
        g_dis[i] = rsqrtf((float)(g_deg_in[i] + 1));  // +1 self-loop; deg >= 1
        int c = g_deg_out[i];
        g_invcnt[i] = 1.0f / (float)(c > 0 ? c : 1);
    }
}

__global__ void fill_kernel(const int* __restrict__ src, const int* __restrict__ dst) {
    int e = blockIdx.x * blockDim.x + threadIdx.x;
    if (e < NE) {
        int s = src[e], d = dst[e];
        int p = atomicAdd(&g_cur_in[d], 1);
        g_col_in[p] = s;
        int q = atomicAdd(&g_cur_out[s], 1);
        g_col_out[q] = d;
    }
}

// ---------------- GEMM: rows x [K] @ [K,64] (optionally two W -> two outs) --
// Tile: 32 rows x (DUAL?128:64) cols per block; 256 threads (tx 0..15, ty 0..15)
// Each thread: 2 rows x (DUAL?8:4) cols, accumulated as f32x2 pairs.
template <int KCHUNKS, bool DUAL, bool BR>
__global__ void gemm_kernel(const float* __restrict__ Xin, int ldx,
                            const float* __restrict__ W0,
                            const float* __restrict__ W1,
                            const float* __restrict__ bias,
                            float* __restrict__ O0,
                            float* __restrict__ O1) {
    constexpr int WCOLS = DUAL ? 128 : 64;
    constexpr int CPT = DUAL ? 8 : 4;   // cols per thread
    __shared__ float Ws[64 * WCOLS];
    __shared__ float Xs[64][34];        // [k][row], pad keeps float2 aligned
    int t = threadIdx.x;
    int tx = t & 15, ty = t >> 4;
    int ntiles = (NN + 31) / 32;
    for (int tile = blockIdx.x; tile < ntiles; tile += gridDim.x) {
        int row0 = tile * 32;
        unsigned long long acc[2][CPT / 2];
        #pragma unroll
        for (int r = 0; r < 2; r++)
            #pragma unroll
            for (int j = 0; j < CPT / 2; j++) acc[r][j] = 0ull;

        #pragma unroll
        for (int kc = 0; kc < KCHUNKS; kc++) {
            __syncthreads();
            for (int i = t; i < 64 * WCOLS; i += 256) {
                int k = i / WCOLS, c = i % WCOLS;
                Ws[i] = (c < 64) ? W0[(kc * 64 + k) * 64 + c]
                                 : W1[(kc * 64 + k) * 64 + (c - 64)];
            }
            for (int i = t; i < 32 * 64; i += 256) {
                int r = i >> 6, k = i & 63;
                int row = row0 + r;
                Xs[k][r] = (row < NN) ? Xin[row * ldx + kc * 64 + k] : 0.f;
            }
            __syncthreads();
            #pragma unroll
            for (int k = 0; k < 64; k++) {
                float2 xv = *(const float2*)&Xs[k][2 * ty];
                unsigned long long xp0 = pack2(xv.x, xv.x);
                unsigned long long xp1 = pack2(xv.y, xv.y);
                const float* wrow = &Ws[k * WCOLS + tx * CPT];
                if (DUAL) {
                    ulonglong2 wa = *(const ulonglong2*)wrow;
                    ulonglong2 wb = *(const ulonglong2*)(wrow + 4);
                    fma2(acc[0][0], xp0, wa.x); fma2(acc[0][1], xp0, wa.y);
                    fma2(acc[0][2], xp0, wb.x); fma2(acc[0][3], xp0, wb.y);
                    fma2(acc[1][0], xp1, wa.x); fma2(acc[1][1], xp1, wa.y);
                    fma2(acc[1][2], xp1, wb.x); fma2(acc[1][3], xp1, wb.y);
                } else {
                    ulonglong2 wa = *(const ulonglong2*)wrow;
                    fma2(acc[0][0], xp0, wa.x); fma2(acc[0][1], xp0, wa.y);
                    fma2(acc[1][0], xp1, wa.x); fma2(acc[1][1], xp1, wa.y);
                }
            }
        }
        #pragma unroll
        for (int rr = 0; rr < 2; rr++) {
            int row = row0 + 2 * ty + rr;
            if (row < NN) {
                #pragma unroll
                for (int j = 0; j < CPT / 2; j++) {
                    float2 vv = unpack2(acc[rr][j]);
                    int c = tx * CPT + 2 * j;
                    if (BR) {
                        vv.x = fmaxf(vv.x + bias[c], 0.f);
                        vv.y = fmaxf(vv.y + bias[c + 1], 0.f);
                    }
                    if (!DUAL || c < 64) {
                        *(float2*)&O0[row * 64 + c] = vv;
                    } else {
                        *(float2*)&O1[row * 64 + (c - 64)] = vv;
                    }
                }
            }
        }
    }
}

// ---------------- conv aggregation (both convs fused), CSR-by-dst ----------
// One warp per node; lane owns features [2*lane, 2*lane+1].
__global__ void aggregate_kernel(const float* __restrict__ bc,
                                 const float* __restrict__ bg) {
    int w = (blockIdx.x * blockDim.x + threadIdx.x) >> 5;
    int lane = threadIdx.x & 31;
    if (w >= NN) return;
    int v = w;
    float dv = g_dis[v];
    int beg = g_rp_in[v], end = g_rp_in[v + 1];
    const float2* XWc2 = (const float2*)g_XWc;
    const float2* XWg2 = (const float2*)g_XWg;
    float2 c0 = XWc2[v * 32 + lane];
    float2 gg0 = XWg2[v * 32 + lane];
    float w0 = dv * dv;  // self-loop weight
    float ax = w0 * c0.x, ay = w0 * c0.y;
    float bx = w0 * gg0.x, by = w0 * gg0.y;
    int e = beg;
    for (; e + 1 < end; e += 2) {
        int s0 = g_col_in[e], s1 = g_col_in[e + 1];
        float we0 = g_dis[s0] * dv, we1 = g_dis[s1] * dv;
        float2 cs0 = XWc2[s0 * 32 + lane];
        float2 gs0 = XWg2[s0 * 32 + lane];
        float2 cs1 = XWc2[s1 * 32 + lane];
        float2 gs1 = XWg2[s1 * 32 + lane];
        ax = fmaf(we0, cs0.x, ax); ay = fmaf(we0, cs0.y, ay);
        bx = fmaf(we0, gs0.x, bx); by = fmaf(we0, gs0.y, by);
        ax = fmaf(we1, cs1.x, ax); ay = fmaf(we1, cs1.y, ay);
        bx = fmaf(we1, gs1.x, bx); by = fmaf(we1, gs1.y, by);
    }
    if (e < end) {
        int s = g_col_in[e];
        float we = g_dis[s] * dv;
        float2 cs = XWc2[s * 32 + lane];
        float2 gs = XWg2[s * 32 + lane];
        ax = fmaf(we, cs.x, ax); ay = fmaf(we, cs.y, ay);
        bx = fmaf(we, gs.x, bx); by = fmaf(we, gs.y, by);
    }
    int f = 2 * lane;
    float2 bcv = make_float2(bc[f], bc[f + 1]);
    float2 bgv = make_float2(bg[f], bg[f + 1]);
    float2* Xn2 = (float2*)g_Xn;
    float2* xg2 = (float2*)g_xg;
    Xn2[v * 32 + lane] = make_float2(fmaxf(ax + bcv.x, 0.f), fmaxf(ay + bcv.y, 0.f));
    xg2[v * 32 + lane] = make_float2(fmaxf(bx + bgv.x, 0.f), fmaxf(by + bgv.y, 0.f));
}

// ---------------- gate (segment over src) + convex combine -----------------
__global__ void gate_kernel() {
    int w = (blockIdx.x * blockDim.x + threadIdx.x) >> 5;
    int lane = threadIdx.x & 31;
    if (w >= NN) return;
    int u = w;
    const float2* xg2 = (const float2*)g_xg;
    float2 xu = xg2[u * 32 + lane];
    int beg = g_rp_out[u], end = g_rp_out[u + 1];
    float sx = 0.f, sy = 0.f;
    int e = beg;
    for (; e + 1 < end; e += 2) {
        int d0 = g_col_out[e], d1 = g_col_out[e + 1];
        float2 x0 = xg2[d0 * 32 + lane];
        float2 x1 = xg2[d1 * 32 + lane];
        float ax = xu.x - x0.x, ay = xu.y - x0.y;
        float cx = xu.x - x1.x, cy = xu.y - x1.y;
        sx = fmaf(ax, ax, sx); sy = fmaf(ay, ay, sy);
        sx = fmaf(cx, cx, sx); sy = fmaf(cy, cy, sy);
    }
    if (e < end) {
        int d = g_col_out[e];
        float2 x0 = xg2[d * 32 + lane];
        float ax = xu.x - x0.x, ay = xu.y - x0.y;
        sx = fmaf(ax, ax, sx); sy = fmaf(ay, ay, sy);
    }
    float ic = g_invcnt[u];
    float tx = tanhf(sx * ic);
    float ty = tanhf(sy * ic);
    float2* X2 = (float2*)g_X;
    const float2* Xn2 = (const float2*)g_Xn;
    float2 xo = X2[u * 32 + lane];
    float2 xn = Xn2[u * 32 + lane];
    X2[u * 32 + lane] = make_float2((1.f - tx) * xo.x + tx * xn.x,
                                    (1.f - ty) * xo.y + ty * xn.y);
}

// ---------------- host side ----------------
extern "C" void kernel_launch(void* const* d_in, const int* in_sizes, int n_in,
                              void* d_out, int out_size) {
    const float* x     = (const float*)d_in[0];
    const int*   ei    = (const int*)d_in[1];
    const float* enc_w = (const float*)d_in[2];
    const float* enc_b = (const float*)d_in[3];
    const float* conv_w = (const float*)d_in[4];
    const float* conv_b = (const float*)d_in[5];
    const float* gg_w  = (const float*)d_in[6];
    const float* gg_b  = (const float*)d_in[7];
    const float* dec_w = (const float*)d_in[8];
    const float* dec_b = (const float*)d_in[9];
    const int* src = ei;
    const int* dst = ei + NE;

    float *pX, *pXWc, *pXWg;
    int *pDegIn, *pDegOut, *pRpIn, *pRpOut, *pCurIn, *pCurOut;
    cudaGetSymbolAddress((void**)&pX, g_X);
    cudaGetSymbolAddress((void**)&pXWc, g_XWc);
    cudaGetSymbolAddress((void**)&pXWg, g_XWg);
    cudaGetSymbolAddress((void**)&pDegIn, g_deg_in);
    cudaGetSymbolAddress((void**)&pDegOut, g_deg_out);
    cudaGetSymbolAddress((void**)&pRpIn, g_rp_in);
    cudaGetSymbolAddress((void**)&pRpOut, g_rp_out);
    cudaGetSymbolAddress((void**)&pCurIn, g_cur_in);
    cudaGetSymbolAddress((void**)&pCurOut, g_cur_out);

    const int TB = 256;
    int nodeBlocks = (NN + TB - 1) / TB;          // 196
    int edgeBlocks = (NE + TB - 1) / TB;          // 3125
    int warpNodeBlocks = (NN * 32 + TB - 1) / TB; // 6250
    int gemmBlocks = (NN + 31) / 32;              // 1563

    // graph preprocessing (runs every launch; graph-replay safe)
    zero_deg_kernel<<<nodeBlocks, TB>>>();
    count_kernel<<<edgeBlocks, TB>>>(src, dst);
    scan_kernel<<<1, 1024>>>(pDegIn, pRpIn, pCurIn);
    scan_kernel<<<1, 1024>>>(pDegOut, pRpOut, pCurOut);
    node_init_kernel<<<nodeBlocks, TB>>>();
    fill_kernel<<<edgeBlocks, TB>>>(src, dst);

    // encoder: X = relu(x @ enc_w + enc_b)
    gemm_kernel<4, false, true><<<gemmBlocks, TB>>>(x, NIN, enc_w, nullptr, enc_b,
                                                    pX, nullptr);

    for (int it = 0; it < DEPTH; it++) {
        gemm_kernel<1, true, false><<<gemmBlocks, TB>>>(pX, NF, conv_w, gg_w,
                                                        nullptr, pXWc, pXWg);
        aggregate_kernel<<<warpNodeBlocks, TB>>>(conv_b, gg_b);
        gate_kernel<<<warpNodeBlocks, TB>>>();
    }

    // decoder: out = relu(X @ dec_w + dec_b)
    gemm_kernel<1, false, true><<<gemmBlocks, TB>>>(pX, NF, dec_w, nullptr, dec_b,
                                                    (float*)d_out, nullptr);
}

// round 3
// speedup vs baseline: 1.1275x; 1.1275x over previous
#include <cuda_runtime.h>

// Problem constants (fixed by the dataset)
#define NN   50000
#define NE   800000
#define NF   64
#define NIN  256
#define DEPTH 4

#define NTOT (2 * NN)                 // concatenated degree array length
#define SCAN_BLOCKS ((NTOT + 1023) / 1024)   // 98

// ---------------- device scratch (static allocation only) ----------------
__device__ float g_X[NN * NF];       // current node features
__device__ float g_XWcg[NN * 128];   // interleaved [c0 c1 g0 g1] per feature pair
__device__ float g_Xn[NN * NF];      // relu(gcn_conv(X, conv_w)) = X_
__device__ float g_xg[NN * NF];      // relu(gcn_conv(X, gg_w))
__device__ float g_dis[NN];          // rsqrt(in_deg + 1)
__device__ float g_invcnt[NN];       // 1 / max(out_deg, 1)
__device__ int   g_deg_in[NN];
__device__ int   g_deg_out[NN];
__device__ int   g_rp_in[NN + 1];
__device__ int   g_rp_out[NN + 1];
__device__ int   g_cur_in[NN];
__device__ int   g_cur_out[NN];
__device__ int   g_col_in[NE];       // src ids, grouped by dst
__device__ int   g_col_out[NE];      // dst ids, grouped by src
__device__ int   g_bsum[128];
__device__ int   g_boff[128];

// ---------------- f32x2 packed-FMA helpers (PTX-only on sm_10x) ----------
__device__ __forceinline__ unsigned long long pack2(float a, float b) {
    unsigned long long r;
    asm("mov.b64 %0, {%1, %2};" : "=l"(r) : "f"(a), "f"(b));
    return r;
}
__device__ __forceinline__ void fma2(unsigned long long& d,
                                     unsigned long long a,
                                     unsigned long long b) {
    asm("fma.rn.f32x2 %0, %1, %2, %0;" : "+l"(d) : "l"(a), "l"(b));
}
__device__ __forceinline__ float2 unpack2(unsigned long long v) {
    float2 r;
    asm("mov.b64 {%0, %1}, %2;" : "=f"(r.x), "=f"(r.y) : "l"(v));
    return r;
}

// ---------------- graph preprocessing ----------------
__global__ void count_kernel(const int* __restrict__ src, const int* __restrict__ dst) {
    int e = blockIdx.x * blockDim.x + threadIdx.x;
    if (e < NE) {
        atomicAdd(&g_deg_out[src[e]], 1);
        atomicAdd(&g_deg_in[dst[e]], 1);
    }
}

__device__ __forceinline__ int load_deg(int i) {
    if (i < NN) return g_deg_in[i];
    if (i < NTOT) return g_deg_out[i - NN];
    return 0;
}

// pass 1: per-block sums of the concatenated degree array (1024 elems/block)
__global__ void scan_p1() {
    __shared__ int ws[32];
    int t = threadIdx.x, lane = t & 31, wid = t >> 5;
    int v = load_deg(blockIdx.x * 1024 + t);
    #pragma unroll
    for (int d = 16; d > 0; d >>= 1) v += __shfl_down_sync(0xffffffffu, v, d);
    if (lane == 0) ws[wid] = v;
    __syncthreads();
    if (wid == 0) {
        int s = (lane < 32) ? ws[lane] : 0;
        #pragma unroll
        for (int d = 16; d > 0; d >>= 1) s += __shfl_down_sync(0xffffffffu, s, d);
        if (lane == 0) g_bsum[blockIdx.x] = s;
    }
}

// pass 2: exclusive scan of the <=128 block sums (one block, 128 threads)
__global__ void scan_p2() {
    __shared__ int ws[4];
    int t = threadIdx.x, lane = t & 31, wid = t >> 5;
    int v = (t < SCAN_BLOCKS) ? g_bsum[t] : 0;
    int x = v;
    #pragma unroll
    for (int d = 1; d < 32; d <<= 1) {
        int y = __shfl_up_sync(0xffffffffu, x, d);
        if (lane >= d) x += y;
    }
    if (lane == 31) ws[wid] = x;
    __syncthreads();
    int add = 0;
    #pragma unroll
    for (int w = 0; w < 4; w++) if (w < wid) add += ws[w];
    g_boff[t] = add + x - v;   // exclusive
}

// pass 3: per-block exclusive scan + global offset -> rowptrs
__global__ void scan_p3() {
    __shared__ int ws[32];
    int t = threadIdx.x, lane = t & 31, wid = t >> 5;
    int i = blockIdx.x * 1024 + t;
    int v = load_deg(i);
    int x = v;
    #pragma unroll
    for (int d = 1; d < 32; d <<= 1) {
        int y = __shfl_up_sync(0xffffffffu, x, d);
        if (lane >= d) x += y;
    }
    if (lane == 31) ws[wid] = x;
    __syncthreads();
    if (wid == 0) {
        int s = ws[lane];
        #pragma unroll
        for (int d = 1; d < 32; d <<= 1) {
            int y = __shfl_up_sync(0xffffffffu, s, d);
            if (lane >= d) s += y;
        }
        ws[lane] = s;
    }
    __syncthreads();
    int pre = (wid > 0) ? ws[wid - 1] : 0;
    int excl = g_boff[blockIdx.x] + pre + x - v;
    if (i < NN) {
        g_rp_in[i] = excl;
        g_cur_in[i] = excl;
    } else if (i < NTOT) {
        g_rp_out[i - NN] = excl - NE;
        g_cur_out[i - NN] = excl - NE;
    }
    if (i == 0) { g_rp_in[NN] = NE; g_rp_out[NN] = NE; }
}

__global__ void node_init_kernel() {
    int i = blockIdx.x * blockDim.x + threadIdx.x;
    if (i < NN) {
        g_dis[i] = rsqrtf((float)(g_deg_in[i] + 1));  // +1 self-loop
        int c = g_deg_out[i];
        g_invcnt[i] = 1.0f / (float)(c > 0 ? c : 1);
    }
}

__global__ void fill_kernel(const int* __restrict__ src, const int* __restrict__ dst) {
    int e = blockIdx.x * blockDim.x + threadIdx.x;
    if (e < NE) {
        int s = src[e], d = dst[e];
        int p = atomicAdd(&g_cur_in[d], 1);
        g_col_in[p] = s;
        int q = atomicAdd(&g_cur_out[s], 1);
        g_col_out[q] = d;
    }
}

// ---------------- GEMM: rows x [K] @ [K,64] (optionally two W -> interleave) -
// Tile: 32 rows x (DUAL?128:64) cols per block; 256 threads (tx 0..15, ty 0..15)
template <int KCHUNKS, bool DUAL, bool BR>
__global__ void gemm_kernel(const float* __restrict__ Xin, int ldx,
                            const float* __restrict__ W0,
                            const float* __restrict__ W1,
                            const float* __restrict__ bias,
                            float* __restrict__ O0) {
    constexpr int WCOLS = DUAL ? 128 : 64;
    constexpr int CPT = DUAL ? 8 : 4;   // cols per thread
    __shared__ float Ws[64 * WCOLS];
    __shared__ float Xs[64][34];        // [k][row], pad keeps float2 aligned
    int t = threadIdx.x;
    int tx = t & 15, ty = t >> 4;
    int ntiles = (NN + 31) / 32;
    for (int tile = blockIdx.x; tile < ntiles; tile += gridDim.x) {
        int row0 = tile * 32;
        unsigned long long acc[2][CPT / 2];
        #pragma unroll
        for (int r = 0; r < 2; r++)
            #pragma unroll
            for (int j = 0; j < CPT / 2; j++) acc[r][j] = 0ull;

        #pragma unroll
        for (int kc = 0; kc < KCHUNKS; kc++) {
            __syncthreads();
            for (int i = t; i < 64 * WCOLS; i += 256) {
                int k = i / WCOLS, c = i % WCOLS;
                Ws[i] = (c < 64) ? W0[(kc * 64 + k) * 64 + c]
                                 : W1[(kc * 64 + k) * 64 + (c - 64)];
            }
            for (int i = t; i < 32 * 64; i += 256) {
                int r = i >> 6, k = i & 63;
                int row = row0 + r;
                Xs[k][r] = (row < NN) ? Xin[row * ldx + kc * 64 + k] : 0.f;
            }
            __syncthreads();
            #pragma unroll
            for (int k = 0; k < 64; k++) {
                float2 xv = *(const float2*)&Xs[k][2 * ty];
                unsigned long long xp0 = pack2(xv.x, xv.x);
                unsigned long long xp1 = pack2(xv.y, xv.y);
                const float* wrow = &Ws[k * WCOLS + tx * CPT];
                if (DUAL) {
                    ulonglong2 wa = *(const ulonglong2*)wrow;
                    ulonglong2 wb = *(const ulonglong2*)(wrow + 4);
                    fma2(acc[0][0], xp0, wa.x); fma2(acc[0][1], xp0, wa.y);
                    fma2(acc[0][2], xp0, wb.x); fma2(acc[0][3], xp0, wb.y);
                    fma2(acc[1][0], xp1, wa.x); fma2(acc[1][1], xp1, wa.y);
                    fma2(acc[1][2], xp1, wb.x); fma2(acc[1][3], xp1, wb.y);
                } else {
                    ulonglong2 wa = *(const ulonglong2*)wrow;
                    fma2(acc[0][0], xp0, wa.x); fma2(acc[0][1], xp0, wa.y);
                    fma2(acc[1][0], xp1, wa.x); fma2(acc[1][1], xp1, wa.y);
                }
            }
        }
        #pragma unroll
        for (int rr = 0; rr < 2; rr++) {
            int row = row0 + 2 * ty + rr;
            if (row < NN) {
                #pragma unroll
                for (int j = 0; j < CPT / 2; j++) {
                    float2 vv = unpack2(acc[rr][j]);
                    int c = tx * CPT + 2 * j;
                    if (BR) {
                        vv.x = fmaxf(vv.x + bias[c], 0.f);
                        vv.y = fmaxf(vv.y + bias[c + 1], 0.f);
                    }
                    if (DUAL) {
                        // interleave: feature pair p of conv at [p*4], gate at [p*4+2]
                        int f = (c < 64) ? c : (c - 64);
                        int off = row * 128 + (f >> 1) * 4 + ((c < 64) ? 0 : 2);
                        *(float2*)&O0[off] = vv;
                    } else {
                        *(float2*)&O0[row * 64 + c] = vv;
                    }
                }
            }
        }
    }
}

// ---------------- conv aggregation (both convs fused), CSR-by-dst ----------
// One warp per node; lane owns feature pair [2*lane, 2*lane+1] of both convs
// via one float4 (c0 c1 g0 g1) per neighbor.
__global__ void aggregate_kernel(const float* __restrict__ bc,
                                 const float* __restrict__ bg) {
    int w = (blockIdx.x * blockDim.x + threadIdx.x) >> 5;
    int lane = threadIdx.x & 31;
    if (w >= NN) return;
    int v = w;
    float dv = g_dis[v];
    int beg = g_rp_in[v], end = g_rp_in[v + 1];
    const float4* M = (const float4*)g_XWcg;
    float4 self = M[v * 32 + lane];
    float w0 = dv * dv;  // self-loop weight
    float ax = w0 * self.x, ay = w0 * self.y;
    float bx = w0 * self.z, by = w0 * self.w;
    int e = beg;
    for (; e + 1 < end; e += 2) {
        int s0 = g_col_in[e], s1 = g_col_in[e + 1];
        float we0 = g_dis[s0] * dv, we1 = g_dis[s1] * dv;
        float4 m0 = M[s0 * 32 + lane];
        float4 m1 = M[s1 * 32 + lane];
        ax = fmaf(we0, m0.x, ax); ay = fmaf(we0, m0.y, ay);
        bx = fmaf(we0, m0.z, bx); by = fmaf(we0, m0.w, by);
        ax = fmaf(we1, m1.x, ax); ay = fmaf(we1, m1.y, ay);
        bx = fmaf(we1, m1.z, bx); by = fmaf(we1, m1.w, by);
    }
    if (e < end) {
        int s = g_col_in[e];
        float we = g_dis[s] * dv;
        float4 m = M[s * 32 + lane];
        ax = fmaf(we, m.x, ax); ay = fmaf(we, m.y, ay);
        bx = fmaf(we, m.z, bx); by = fmaf(we, m.w, by);
    }
    int f = 2 * lane;
    float2* Xn2 = (float2*)g_Xn;
    float2* xg2 = (float2*)g_xg;
    Xn2[v * 32 + lane] = make_float2(fmaxf(ax + bc[f], 0.f), fmaxf(ay + bc[f + 1], 0.f));
    xg2[v * 32 + lane] = make_float2(fmaxf(bx + bg[f], 0.f), fmaxf(by + bg[f + 1], 0.f));
}

// ---------------- gate (segment over src) + convex combine -----------------
__global__ void gate_kernel() {
    int w = (blockIdx.x * blockDim.x + threadIdx.x) >> 5;
    int lane = threadIdx.x & 31;
    if (w >= NN) return;
    int u = w;
    const float2* xg2 = (const float2*)g_xg;
    float2 xu = xg2[u * 32 + lane];
    int beg = g_rp_out[u], end = g_rp_out[u + 1];
    float sx = 0.f, sy = 0.f;
    int e = beg;
    for (; e + 1 < end; e += 2) {
        int d0 = g_col_out[e], d1 = g_col_out[e + 1];
        float2 x0 = xg2[d0 * 32 + lane];
        float2 x1 = xg2[d1 * 32 + lane];
        float ax = xu.x - x0.x, ay = xu.y - x0.y;
        float cx = xu.x - x1.x, cy = xu.y - x1.y;
        sx = fmaf(ax, ax, sx); sy = fmaf(ay, ay, sy);
        sx = fmaf(cx, cx, sx); sy = fmaf(cy, cy, sy);
    }
    if (e < end) {
        int d = g_col_out[e];
        float2 x0 = xg2[d * 32 + lane];
        float ax = xu.x - x0.x, ay = xu.y - x0.y;
        sx = fmaf(ax, ax, sx); sy = fmaf(ay, ay, sy);
    }
    float ic = g_invcnt[u];
    float tx = tanhf(sx * ic);
    float ty = tanhf(sy * ic);
    float2* X2 = (float2*)g_X;
    const float2* Xn2 = (const float2*)g_Xn;
    float2 xo = X2[u * 32 + lane];
    float2 xn = Xn2[u * 32 + lane];
    X2[u * 32 + lane] = make_float2((1.f - tx) * xo.x + tx * xn.x,
                                    (1.f - ty) * xo.y + ty * xn.y);
}

// ---------------- host side ----------------
extern "C" void kernel_launch(void* const* d_in, const int* in_sizes, int n_in,
                              void* d_out, int out_size) {
    const float* x      = (const float*)d_in[0];
    const int*   ei     = (const int*)d_in[1];
    const float* enc_w  = (const float*)d_in[2];
    const float* enc_b  = (const float*)d_in[3];
    const float* conv_w = (const float*)d_in[4];
    const float* conv_b = (const float*)d_in[5];
    const float* gg_w   = (const float*)d_in[6];
    const float* gg_b   = (const float*)d_in[7];
    const float* dec_w  = (const float*)d_in[8];
    const float* dec_b  = (const float*)d_in[9];
    const int* src = ei;
    const int* dst = ei + NE;

    float *pX, *pXWcg;
    int *pDegIn, *pDegOut;
    cudaGetSymbolAddress((void**)&pX, g_X);
    cudaGetSymbolAddress((void**)&pXWcg, g_XWcg);
    cudaGetSymbolAddress((void**)&pDegIn, g_deg_in);
    cudaGetSymbolAddress((void**)&pDegOut, g_deg_out);

    const int TB = 256;
    int nodeBlocks = (NN + TB - 1) / TB;          // 196
    int edgeBlocks = (NE + TB - 1) / TB;          // 3125
    int warpNodeBlocks = (NN * 32 + TB - 1) / TB; // 6250
    int gemmBlocks = (NN + 31) / 32;              // 1563

    // graph preprocessing (runs every launch; graph-replay safe)
    cudaMemsetAsync(pDegIn, 0, NN * sizeof(int));
    cudaMemsetAsync(pDegOut, 0, NN * sizeof(int));
    count_kernel<<<edgeBlocks, TB>>>(src, dst);
    scan_p1<<<SCAN_BLOCKS, 1024>>>();
    scan_p2<<<1, 128>>>();
    scan_p3<<<SCAN_BLOCKS, 1024>>>();
    node_init_kernel<<<nodeBlocks, TB>>>();
    fill_kernel<<<edgeBlocks, TB>>>(src, dst);

    // encoder: X = relu(x @ enc_w + enc_b)
    gemm_kernel<4, false, true><<<gemmBlocks, TB>>>(x, NIN, enc_w, nullptr, enc_b, pX);

    for (int it = 0; it < DEPTH; it++) {
        gemm_kernel<1, true, false><<<gemmBlocks, TB>>>(pX, NF, conv_w, gg_w,
                                                        nullptr, pXWcg);
        aggregate_kernel<<<warpNodeBlocks, TB>>>(conv_b, gg_b);
        gate_kernel<<<warpNodeBlocks, TB>>>();
    }

    // decoder: out = relu(X @ dec_w + dec_b)
    gemm_kernel<1, false, true><<<gemmBlocks, TB>>>(pX, NF, dec_w, nullptr, dec_b,
                                                    (float*)d_out);
}